// round 10
// baseline (speedup 1.0000x reference)
#include <cuda_runtime.h>
#include <cuda_fp16.h>
#include <math.h>
#include <stdint.h>

#define BATCH 8
#define SEQ   2048
#define DIM   320
#define NHEAD 5
#define HDIM  64
#define FFD   864
#define NLAYER 6
#define KSEL  1638
#define NTOK  (BATCH*SEQ)      // 16384
#define NSEL  (BATCH*KSEL)     // 13104
#define QKVN  (3*DIM)          // 960

// weight split buffer offsets (elements)
#define OFF_QKV  0
#define LEN_QKV  (NLAYER*QKVN*DIM)
#define OFF_WO   (OFF_QKV + LEN_QKV)
#define LEN_WO   (NLAYER*DIM*DIM)
#define OFF_GU   (OFF_WO + LEN_WO)
#define LEN_GU   (NLAYER*2*FFD*DIM)
#define OFF_DOWN (OFF_GU + LEN_GU)
#define LEN_DOWN (NLAYER*DIM*FFD)
#define W_TOTAL  (OFF_DOWN + LEN_DOWN)

// ---------------- scratch ----------------
__device__ __half g_ahi[(size_t)NTOK*DIM];
__device__ __half g_alo[(size_t)NTOK*DIM];
__device__ __half g_shi[(size_t)NSEL*FFD];
__device__ __half g_slo[(size_t)NSEL*FFD];
__device__ __half g_whi[W_TOTAL];
__device__ __half g_wlo[W_TOTAL];
__device__ float g_qkv[(size_t)NTOK*QKVN];
__device__ __half g_qkh[(size_t)NTOK*2*DIM];
__device__ __half g_qkl[(size_t)NTOK*2*DIM];
__device__ __half g_vth[(size_t)BATCH*NHEAD*HDIM*SEQ];
__device__ __half g_vtl[(size_t)BATCH*NHEAD*HDIM*SEQ];
__device__ float g_cos[SEQ*32];
__device__ float g_sin[SEQ*32];
__device__ int   g_tk_idx[BATCH*KSEL];
__device__ float g_tk_p[BATCH*KSEL];
__device__ float g_probs[NTOK];

__device__ __forceinline__ void split_h(float v, __half& h, __half& l) {
    h = __float2half_rn(v);
    l = __float2half_rn(v - __half2float(h));
}

// ================= PTX helpers =================
__device__ __forceinline__ uint32_t smem_u32(const void* p) {
    uint32_t a;
    asm("{ .reg .u64 t; cvta.to.shared.u64 t, %1; cvt.u32.u64 %0, t; }" : "=r"(a) : "l"(p));
    return a;
}
__device__ __forceinline__ void cp16(uint32_t dst, const void* src) {
    asm volatile("cp.async.cg.shared.global [%0], [%1], 16;" :: "r"(dst), "l"(src) : "memory");
}
__device__ __forceinline__ void ldsm4(uint32_t* r, uint32_t addr) {
    asm volatile("ldmatrix.sync.aligned.m8n8.x4.shared.b16 {%0,%1,%2,%3}, [%4];"
        : "=r"(r[0]), "=r"(r[1]), "=r"(r[2]), "=r"(r[3]) : "r"(addr));
}
__device__ __forceinline__ void mma16816(float* c, const uint32_t* a, const uint32_t* b) {
    asm volatile("mma.sync.aligned.m16n8k16.row.col.f32.f16.f16.f32 "
        "{%0,%1,%2,%3}, {%4,%5,%6,%7}, {%8,%9}, {%0,%1,%2,%3};"
        : "+f"(c[0]), "+f"(c[1]), "+f"(c[2]), "+f"(c[3])
        : "r"(a[0]), "r"(a[1]), "r"(a[2]), "r"(a[3]), "r"(b[0]), "r"(b[1]));
}
__device__ __forceinline__ uint32_t sw_addr(uint32_t base, int row, int chunk) {
    return base + (uint32_t)(row*128) + (uint32_t)(((chunk ^ (row & 7)))*16);
}

// ================= fp16x3 tensor-core GEMM (3-stage, ldmatrix, 2 CTAs/SM) =================
// mode 0: C = A@B^T   mode 1: C += A@B^T
// mode 2: swiglu (B rows interleaved gate/up) -> Dhi/Dlo [M,FFD]
// mode 3: down + scatter into x
__global__ __launch_bounds__(256, 2)
void gemm_h3_k(const __half* __restrict__ Ahi, const __half* __restrict__ Alo,
               const __half* __restrict__ Bhi, const __half* __restrict__ Blo,
               float* __restrict__ C, __half* __restrict__ Dhi, __half* __restrict__ Dlo,
               int M, int N, int K, int mode)
{
    extern __shared__ char smem_raw[];
    uint32_t sb = (smem_u32(smem_raw) + 127u) & ~127u;

    const int t = threadIdx.x, lane = t & 31, wid = t >> 5;
    const int warp_m = wid & 1, warp_n = wid >> 1;
    const int m0 = blockIdx.y*128, n0 = blockIdx.x*128;
    const int T = K >> 5;
    const int l4 = lane >> 2, lm = lane & 3;

    const int lrow = t >> 1;
    const int lhalf = t & 1;
    const int aRow = min(m0 + lrow, M-1);
    const int bRow = min(n0 + lrow, N-1);
    const __half* aSrc = (lhalf ? Alo : Ahi) + (size_t)aRow*K;
    const __half* bSrc = (lhalf ? Blo : Bhi) + (size_t)bRow*K;
    uint32_t aDstBase = sb + (uint32_t)lrow*128u;
    uint32_t bDstBase = sb + 16384u + (uint32_t)lrow*128u;

    auto load_stage = [&](int kt, int s) {
        uint32_t so = (uint32_t)s*32768u;
        int k0 = kt*32;
        #pragma unroll
        for (int c4 = 0; c4 < 4; c4++) {
            int chunk = lhalf*4 + c4;
            uint32_t phys = (uint32_t)((chunk ^ (lrow & 7)) * 16);
            cp16(aDstBase + so + phys, aSrc + k0 + c4*8);
            cp16(bDstBase + so + phys, bSrc + k0 + c4*8);
        }
        asm volatile("cp.async.commit_group;" ::: "memory");
    };

    float accf[4][4][4];
    #pragma unroll
    for (int i = 0; i < 4; i++)
        #pragma unroll
        for (int j = 0; j < 4; j++)
            #pragma unroll
            for (int r = 0; r < 4; r++) accf[i][j][r] = 0.f;

    load_stage(0, 0);
    if (T > 1) load_stage(1, 1);

    const int rAl = (lane & 15);
    const int rBl = (lane & 7) + ((lane >> 4) << 3);
    const int chSelA = lane >> 4;
    const int chSelB = (lane >> 3) & 1;

    for (int kt = 0; kt < T; kt++) {
        int s = kt % 3;
        if (kt + 2 < T) {
            load_stage(kt + 2, (kt + 2) % 3);
            asm volatile("cp.async.wait_group 2;" ::: "memory");
        } else if (kt + 1 < T) {
            asm volatile("cp.async.wait_group 1;" ::: "memory");
        } else {
            asm volatile("cp.async.wait_group 0;" ::: "memory");
        }
        __syncthreads();
        uint32_t Ab = sb + (uint32_t)s*32768u;
        uint32_t Bb = Ab + 16384u;
        #pragma unroll
        for (int ks = 0; ks < 2; ks++) {
            int chAh = ks*2 + chSelA, chAl = chAh + 4;
            int chBh = ks*2 + chSelB, chBl = chBh + 4;
            uint32_t BH[2][4], BL[2][4];
            #pragma unroll
            for (int nfp = 0; nfp < 2; nfp++) {
                int row = warp_n*32 + nfp*16 + rBl;
                ldsm4(BH[nfp], sw_addr(Bb, row, chBh));
                ldsm4(BL[nfp], sw_addr(Bb, row, chBl));
            }
            #pragma unroll
            for (int mf = 0; mf < 4; mf++) {
                int row = warp_m*64 + mf*16 + rAl;
                uint32_t AH4[4], AL4[4];
                ldsm4(AH4, sw_addr(Ab, row, chAh));
                ldsm4(AL4, sw_addr(Ab, row, chAl));
                // pass-major ordering: same-accumulator distance = 4
                mma16816(accf[mf][0], AH4, BH[0] + 0);
                mma16816(accf[mf][1], AH4, BH[0] + 2);
                mma16816(accf[mf][2], AH4, BH[1] + 0);
                mma16816(accf[mf][3], AH4, BH[1] + 2);
                mma16816(accf[mf][0], AH4, BL[0] + 0);
                mma16816(accf[mf][1], AH4, BL[0] + 2);
                mma16816(accf[mf][2], AH4, BL[1] + 0);
                mma16816(accf[mf][3], AH4, BL[1] + 2);
                mma16816(accf[mf][0], AL4, BH[0] + 0);
                mma16816(accf[mf][1], AL4, BH[0] + 2);
                mma16816(accf[mf][2], AL4, BH[1] + 0);
                mma16816(accf[mf][3], AL4, BH[1] + 2);
            }
        }
        __syncthreads();
    }

    // ---- epilogue ----
    #pragma unroll
    for (int mf = 0; mf < 4; mf++) {
        int r0 = m0 + warp_m*64 + mf*16 + l4;
        int r1 = r0 + 8;
        #pragma unroll
        for (int nf = 0; nf < 4; nf++) {
            int c = n0 + warp_n*32 + nf*8 + lm*2;
            if (c >= N) continue;
            float v0 = accf[mf][nf][0], v1 = accf[mf][nf][1];
            float v2 = accf[mf][nf][2], v3 = accf[mf][nf][3];
            if (mode <= 1) {
                if (r0 < M) {
                    float* p = C + (size_t)r0*N + c;
                    if (mode) { v0 += p[0]; v1 += p[1]; }
                    p[0] = v0; p[1] = v1;
                }
                if (r1 < M) {
                    float* p = C + (size_t)r1*N + c;
                    if (mode) { v2 += p[0]; v3 += p[1]; }
                    p[0] = v2; p[1] = v3;
                }
            } else if (mode == 2) {
                int j = c >> 1;
                if (r0 < M) {
                    float o = (v0 / (1.f + expf(-v0))) * v1;
                    __half h, l; split_h(o, h, l);
                    Dhi[(size_t)r0*FFD + j] = h; Dlo[(size_t)r0*FFD + j] = l;
                }
                if (r1 < M) {
                    float o = (v2 / (1.f + expf(-v2))) * v3;
                    __half h, l; split_h(o, h, l);
                    Dhi[(size_t)r1*FFD + j] = h; Dlo[(size_t)r1*FFD + j] = l;
                }
            } else {
                if (r0 < M) {
                    int b = r0 / KSEL;
                    float pp = g_tk_p[r0];
                    float* p = C + ((size_t)b*SEQ + g_tk_idx[r0])*DIM + c;
                    p[0] += v0*pp; p[1] += v1*pp;
                }
                if (r1 < M) {
                    int b = r1 / KSEL;
                    float pp = g_tk_p[r1];
                    float* p = C + ((size_t)b*SEQ + g_tk_idx[r1])*DIM + c;
                    p[0] += v2*pp; p[1] += v3*pp;
                }
            }
        }
    }
}

// ================= small kernels =================
__global__ void rope_table_k() {
    int i = blockIdx.x*blockDim.x + threadIdx.x;
    if (i >= SEQ*32) return;
    int s = i >> 5, d = i & 31;
    double freq = exp(-((double)(2*d)/(double)HDIM) * log(10000.0));
    double a = (double)s * freq;
    g_cos[i] = (float)cos(a);
    g_sin[i] = (float)sin(a);
}

__global__ void embed_k(const int* __restrict__ ids, const int* __restrict__ iter,
                        const float* __restrict__ emb, const float* __restrict__ iter_emb,
                        float* __restrict__ x) {
    int i = blockIdx.x*blockDim.x + threadIdx.x;
    if (i >= NTOK*DIM) return;
    int tok = i / DIM, d = i - tok*DIM;
    int it = iter[0];
    float v = emb[(size_t)ids[tok]*DIM + d];
    if (it < 8) v += iter_emb[(size_t)it*DIM + d];
    x[i] = v;
}

__global__ void split_k(const float* __restrict__ src, __half* __restrict__ hi,
                        __half* __restrict__ lo, int n) {
    int i = blockIdx.x*blockDim.x + threadIdx.x;
    if (i >= n) return;
    __half h, l; split_h(src[i], h, l);
    hi[i] = h; lo[i] = l;
}

__global__ void split_gu_int_k(const float* __restrict__ gw, const float* __restrict__ uw,
                               __half* __restrict__ hi, __half* __restrict__ lo) {
    int i = blockIdx.x*blockDim.x + threadIdx.x;
    if (i >= NLAYER*2*FFD*DIM) return;
    int l = i / (2*FFD*DIM), rr = i % (2*FFD*DIM);
    int row = rr / DIM, d = rr - row*DIM;
    int j = row >> 1;
    const float* src = (row & 1) ? uw : gw;
    float a = src[(size_t)l*FFD*DIM + (size_t)j*DIM + d];
    __half h, lw; split_h(a, h, lw);
    hi[i] = h; lo[i] = lw;
}

__global__ void rmsnorm_split_k(const float* __restrict__ in, const float* __restrict__ w,
                                __half* __restrict__ ohi, __half* __restrict__ olo, int gather) {
    int r = blockIdx.x, t = threadIdx.x;   // 320 threads
    size_t src;
    if (gather) {
        int b = r / KSEL;
        src = ((size_t)b*SEQ + g_tk_idx[r]) * DIM;
    } else {
        src = (size_t)r * DIM;
    }
    float v = in[src + t];
    float sq = v*v;
    #pragma unroll
    for (int o = 16; o > 0; o >>= 1) sq += __shfl_down_sync(0xffffffffu, sq, o);
    __shared__ float wsum[10];
    __shared__ float s_inv;
    if ((t & 31) == 0) wsum[t >> 5] = sq;
    __syncthreads();
    if (t == 0) {
        float s = 0.f;
        #pragma unroll
        for (int i = 0; i < 10; i++) s += wsum[i];
        s_inv = rsqrtf(s / (float)DIM + 1e-6f);
    }
    __syncthreads();
    float y = w[t] * v * s_inv;
    __half h, l; split_h(y, h, l);
    ohi[(size_t)r*DIM + t] = h;
    olo[(size_t)r*DIM + t] = l;
}

__global__ void rmsnorm_plain_k(const float* __restrict__ in, const float* __restrict__ w,
                                float* __restrict__ out) {
    int r = blockIdx.x, t = threadIdx.x;
    float v = in[(size_t)r*DIM + t];
    float sq = v*v;
    #pragma unroll
    for (int o = 16; o > 0; o >>= 1) sq += __shfl_down_sync(0xffffffffu, sq, o);
    __shared__ float wsum[10];
    __shared__ float s_inv;
    if ((t & 31) == 0) wsum[t >> 5] = sq;
    __syncthreads();
    if (t == 0) {
        float s = 0.f;
        #pragma unroll
        for (int i = 0; i < 10; i++) s += wsum[i];
        s_inv = rsqrtf(s / (float)DIM + 1e-6f);
    }
    __syncthreads();
    out[(size_t)r*DIM + t] = w[t] * v * s_inv;
}

// ---- rope + split q/k + transpose/split v ----
__global__ __launch_bounds__(256)
void rope_split_k(const float* __restrict__ qkv) {
    __shared__ float vt[64][65];
    int st = blockIdx.x*64, h = blockIdx.y, b = blockIdx.z;
    int t = threadIdx.x;
    const float* base = qkv + ((size_t)b*SEQ + st)*QKVN;

    #pragma unroll
    for (int k = 0; k < 16; k++) {
        int i = t + k*256;
        int s = i >> 6, d = i & 63;
        vt[d][s] = base[(size_t)s*QKVN + 2*DIM + h*HDIM + d];
    }
    __syncthreads();
    {
        size_t vbase = ((size_t)(b*NHEAD + h))*HDIM*SEQ;
        #pragma unroll
        for (int k = 0; k < 16; k++) {
            int i = t + k*256;
            int d = i >> 6, s = i & 63;
            float v = vt[d][s];
            __half hh, ll; split_h(v, hh, ll);
            size_t o = vbase + (size_t)d*SEQ + st + s;
            g_vth[o] = hh; g_vtl[o] = ll;
        }
    }
    #pragma unroll
    for (int part = 0; part < 2; part++) {
        #pragma unroll
        for (int k = 0; k < 8; k++) {
            int i = t + k*256;
            int tok = i >> 5, d = i & 31;
            int s = st + tok;
            float c = g_cos[s*32 + d], sn = g_sin[s*32 + d];
            const float* p = base + (size_t)tok*QKVN + part*DIM + h*HDIM;
            float a = p[d], bb = p[d+32];
            float o0 = a*c - bb*sn;
            float o1 = bb*c + a*sn;
            if (part == 0) { o0 *= 0.125f; o1 *= 0.125f; }
            size_t ob = ((size_t)b*SEQ + s)*(2*DIM) + part*DIM + h*HDIM;
            __half h0, l0, h1, l1;
            split_h(o0, h0, l0); split_h(o1, h1, l1);
            g_qkh[ob + d] = h0;      g_qkl[ob + d] = l0;
            g_qkh[ob + d + 32] = h1; g_qkl[ob + d + 32] = l1;
        }
    }
}

// ---------------- tensor-core flash attention: 128-q tile, 256 threads ----------------
#define FA_SMEM (32768 + 2*32768 + 128)
__global__ __launch_bounds__(256, 2)
void fattn_tc_k(__half* __restrict__ ohi, __half* __restrict__ olo) {
    extern __shared__ char smem_raw[];
    uint32_t sb = (smem_u32(smem_raw) + 127u) & ~127u;
    const uint32_t QH = sb, QL = sb + 16384;
    const int t = threadIdx.x, lane = t & 31, warp = t >> 5;
    const int l4 = lane >> 2, lm = lane & 3;
    const int wr = warp*16;
    const int qt = gridDim.x - 1 - blockIdx.x;
    const int h = blockIdx.y, b = blockIdx.z;
    const int q0 = qt*128;
    const int ktmax = 2*qt + 1;

    {
        int row = t & 127, cg = t >> 7;
        size_t qoff = ((size_t)b*SEQ + q0 + row)*(2*DIM) + h*HDIM;
        #pragma unroll
        for (int c4 = 0; c4 < 4; c4++) {
            int c = cg*4 + c4;
            uint32_t phys = (uint32_t)(row*128) + (uint32_t)(((c ^ (row&7)))*16);
            cp16(QH + phys, g_qkh + qoff + c*8);
            cp16(QL + phys, g_qkl + qoff + c*8);
        }
    }
    const int lr = t & 63, cg2 = t >> 6;
    size_t vtb = ((size_t)(b*NHEAD + h))*HDIM*SEQ + (size_t)lr*SEQ;

    auto load_stage = [&](int kt, int s) {
        uint32_t sbase = sb + 32768u + (uint32_t)s*32768u;
        int k0 = kt*64;
        size_t koff = ((size_t)b*SEQ + k0 + lr)*(2*DIM) + DIM + h*HDIM;
        #pragma unroll
        for (int c4 = 0; c4 < 2; c4++) {
            int c = cg2*2 + c4;
            uint32_t phys = (uint32_t)(lr*128) + (uint32_t)(((c ^ (lr&7)))*16);
            cp16(sbase          + phys, g_qkh + koff + c*8);
            cp16(sbase +  8192u + phys, g_qkl + koff + c*8);
            cp16(sbase + 16384u + phys, g_vth + vtb + k0 + c*8);
            cp16(sbase + 24576u + phys, g_vtl + vtb + k0 + c*8);
        }
        asm volatile("cp.async.commit_group;" ::: "memory");
    };

    load_stage(0, 0);

    float oacc[8][4];
    #pragma unroll
    for (int i = 0; i < 8; i++)
        #pragma unroll
        for (int j = 0; j < 4; j++) oacc[i][j] = 0.f;
    float m0 = -1e30f, m1 = -1e30f, l0 = 0.f, l1 = 0.f;

    const int rAl = (lane & 15);
    const int rBl = (lane & 7) + ((lane >> 4) << 3);
    const int chSelA = lane >> 4;
    const int chSelB = (lane >> 3) & 1;

    for (int kt = 0; kt <= ktmax; kt++) {
        int s = kt & 1;
        if (kt < ktmax) {
            load_stage(kt + 1, s ^ 1);
            asm volatile("cp.async.wait_group 1;" ::: "memory");
        } else {
            asm volatile("cp.async.wait_group 0;" ::: "memory");
        }
        __syncthreads();
        uint32_t KHs = sb + 32768u + (uint32_t)s*32768u;
        uint32_t KLs = KHs + 8192u, VHs = KHs + 16384u, VLs = KHs + 24576u;
        int k0 = kt*64;

        // ---- S = Q K^T (fp16x3) ----
        float sacc[8][4];
        #pragma unroll
        for (int i = 0; i < 8; i++)
            #pragma unroll
            for (int j = 0; j < 4; j++) sacc[i][j] = 0.f;

        #pragma unroll
        for (int ks = 0; ks < 4; ks++) {
            int chA = ks*2 + chSelA;
            int chB = ks*2 + chSelB;
            uint32_t aqh[4], aql[4];
            int rowq = wr + rAl;
            ldsm4(aqh, sw_addr(QH, rowq, chA));
            ldsm4(aql, sw_addr(QL, rowq, chA));
            #pragma unroll
            for (int nfp = 0; nfp < 4; nfp++) {
                int rowk = nfp*16 + rBl;
                uint32_t bh4[4], bl4[4];
                ldsm4(bh4, sw_addr(KHs, rowk, chB));
                ldsm4(bl4, sw_addr(KLs, rowk, chB));
                // pass-major over sub: same-acc distance 2
                mma16816(sacc[nfp*2+0], aqh, bh4 + 0);
                mma16816(sacc[nfp*2+1], aqh, bh4 + 2);
                mma16816(sacc[nfp*2+0], aqh, bl4 + 0);
                mma16816(sacc[nfp*2+1], aqh, bl4 + 2);
                mma16816(sacc[nfp*2+0], aql, bh4 + 0);
                mma16816(sacc[nfp*2+1], aql, bh4 + 2);
            }
        }

        if (k0 + 63 > q0 + wr) {
            int r0g = q0 + wr + l4, r1g = r0g + 8;
            #pragma unroll
            for (int nf = 0; nf < 8; nf++) {
                int c = k0 + nf*8 + lm*2;
                if (c     > r0g) sacc[nf][0] = -1e30f;
                if (c + 1 > r0g) sacc[nf][1] = -1e30f;
                if (c     > r1g) sacc[nf][2] = -1e30f;
                if (c + 1 > r1g) sacc[nf][3] = -1e30f;
            }
        }

        // ---- online softmax ----
        float mx0 = -1e30f, mx1 = -1e30f;
        #pragma unroll
        for (int nf = 0; nf < 8; nf++) {
            mx0 = fmaxf(mx0, fmaxf(sacc[nf][0], sacc[nf][1]));
            mx1 = fmaxf(mx1, fmaxf(sacc[nf][2], sacc[nf][3]));
        }
        mx0 = fmaxf(mx0, __shfl_xor_sync(0xffffffffu, mx0, 1));
        mx0 = fmaxf(mx0, __shfl_xor_sync(0xffffffffu, mx0, 2));
        mx1 = fmaxf(mx1, __shfl_xor_sync(0xffffffffu, mx1, 1));
        mx1 = fmaxf(mx1, __shfl_xor_sync(0xffffffffu, mx1, 2));
        float mn0 = fmaxf(m0, mx0), mn1 = fmaxf(m1, mx1);
        float cr0 = __expf(m0 - mn0), cr1 = __expf(m1 - mn1);
        m0 = mn0; m1 = mn1;
        float rs0 = 0.f, rs1 = 0.f;
        #pragma unroll
        for (int nf = 0; nf < 8; nf++) {
            sacc[nf][0] = __expf(sacc[nf][0] - mn0); rs0 += sacc[nf][0];
            sacc[nf][1] = __expf(sacc[nf][1] - mn0); rs0 += sacc[nf][1];
            sacc[nf][2] = __expf(sacc[nf][2] - mn1); rs1 += sacc[nf][2];
            sacc[nf][3] = __expf(sacc[nf][3] - mn1); rs1 += sacc[nf][3];
        }
        rs0 += __shfl_xor_sync(0xffffffffu, rs0, 1);
        rs0 += __shfl_xor_sync(0xffffffffu, rs0, 2);
        rs1 += __shfl_xor_sync(0xffffffffu, rs1, 1);
        rs1 += __shfl_xor_sync(0xffffffffu, rs1, 2);
        l0 = l0*cr0 + rs0;
        l1 = l1*cr1 + rs1;
        #pragma unroll
        for (int df = 0; df < 8; df++) {
            oacc[df][0] *= cr0; oacc[df][1] *= cr0;
            oacc[df][2] *= cr1; oacc[df][3] *= cr1;
        }

        // ---- O += P V (fp16x3) ----
        #pragma unroll
        for (int ks = 0; ks < 4; ks++) {
            uint32_t aPh[4], aPl[4];
            #pragma unroll
            for (int h2 = 0; h2 < 2; h2++) {
                int nf = 2*ks + h2;
                __half h0, e0, h1, e1, h2h, e2, h3, e3;
                split_h(sacc[nf][0], h0, e0); split_h(sacc[nf][1], h1, e1);
                split_h(sacc[nf][2], h2h, e2); split_h(sacc[nf][3], h3, e3);
                __half2 ph01 = __halves2half2(h0, h1), pl01 = __halves2half2(e0, e1);
                __half2 ph23 = __halves2half2(h2h, h3), pl23 = __halves2half2(e2, e3);
                aPh[h2*2 + 0] = *(uint32_t*)&ph01;
                aPh[h2*2 + 1] = *(uint32_t*)&ph23;
                aPl[h2*2 + 0] = *(uint32_t*)&pl01;
                aPl[h2*2 + 1] = *(uint32_t*)&pl23;
            }
            int chB = ks*2 + chSelB;
            #pragma unroll
            for (int dfp = 0; dfp < 4; dfp++) {
                int rowv = dfp*16 + rBl;
                uint32_t bh4[4], bl4[4];
                ldsm4(bh4, sw_addr(VHs, rowv, chB));
                ldsm4(bl4, sw_addr(VLs, rowv, chB));
                mma16816(oacc[dfp*2+0], aPh, bh4 + 0);
                mma16816(oacc[dfp*2+1], aPh, bh4 + 2);
                mma16816(oacc[dfp*2+0], aPh, bl4 + 0);
                mma16816(oacc[dfp*2+1], aPh, bl4 + 2);
                mma16816(oacc[dfp*2+0], aPl, bh4 + 0);
                mma16816(oacc[dfp*2+1], aPl, bh4 + 2);
            }
        }
        __syncthreads();
    }

    float inv0 = 1.f / l0, inv1 = 1.f / l1;
    int r0 = q0 + wr + l4, r1 = r0 + 8;
    #pragma unroll
    for (int df = 0; df < 8; df++) {
        int d = df*8 + lm*2;
        float v0 = oacc[df][0]*inv0, v1 = oacc[df][1]*inv0;
        float v2 = oacc[df][2]*inv1, v3 = oacc[df][3]*inv1;
        __half h0, e0, h1, e1, h2, e2, h3, e3;
        split_h(v0, h0, e0); split_h(v1, h1, e1);
        split_h(v2, h2, e2); split_h(v3, h3, e3);
        size_t o0 = ((size_t)b*SEQ + r0)*DIM + h*HDIM + d;
        size_t o1 = ((size_t)b*SEQ + r1)*DIM + h*HDIM + d;
        *(__half2*)(ohi + o0) = __halves2half2(h0, h1);
        *(__half2*)(olo + o0) = __halves2half2(e0, e1);
        *(__half2*)(ohi + o1) = __halves2half2(h2, h3);
        *(__half2*)(olo + o1) = __halves2half2(e2, e3);
    }
}

// ---------------- router + topk ----------------
__global__ __launch_bounds__(256)
void router_prob_k(const float* __restrict__ x, const float* __restrict__ rw,
                   float* __restrict__ probs) {
    int tok = blockIdx.x*8 + (threadIdx.x >> 5);
    int lane = threadIdx.x & 31;
    if (tok >= NTOK) return;
    const float* row = x + (size_t)tok*DIM;
    float acc = 0.f;
    #pragma unroll
    for (int i = 0; i < 10; i++) acc += row[lane + 32*i]*rw[lane + 32*i];
    #pragma unroll
    for (int o = 16; o > 0; o >>= 1) acc += __shfl_xor_sync(0xffffffffu, acc, o);
    if (lane == 0) probs[tok] = 1.f/(1.f + expf(-acc));
}

// radix-select top-k: probs in (0,1) -> positive floats, uint bit compare == float compare.
// Selects KSEL largest (prob desc, ties -> smaller idx), matching jax.lax.top_k's stable order.
__global__ __launch_bounds__(1024)
void topk_k(const float* __restrict__ probs) {
    int b = blockIdx.x, t = threadIdx.x;
    __shared__ uint32_t keys[SEQ];
    __shared__ int hist[256];
    __shared__ uint32_t s_prefix;
    __shared__ int s_remaining;
    __shared__ int s_cnt;

    for (int s = t; s < SEQ; s += 1024) keys[s] = __float_as_uint(probs[b*SEQ + s]);
    if (t == 0) { s_prefix = 0; s_remaining = KSEL; s_cnt = 0; }
    __syncthreads();

    // 4 radix passes, top byte first
    for (int pass = 0; pass < 4; pass++) {
        int shift = 24 - pass*8;
        uint32_t mask = (pass == 0) ? 0u : (0xFFFFFFFFu << (shift + 8));
        if (t < 256) hist[t] = 0;
        __syncthreads();
        uint32_t pfx = s_prefix;
        for (int s = t; s < SEQ; s += 1024) {
            uint32_t kk = keys[s];
            if ((kk & mask) == (pfx & mask))
                atomicAdd(&hist[(kk >> shift) & 255], 1);
        }
        __syncthreads();
        if (t == 0) {
            int acc = 0, bin = 255;
            for (; bin > 0; bin--) {
                if (acc + hist[bin] >= s_remaining) break;
                acc += hist[bin];
            }
            s_prefix |= (uint32_t)bin << shift;
            s_remaining -= acc;
        }
        __syncthreads();
    }

    uint32_t T = s_prefix;      // k-th largest key value
    int rem = s_remaining;      // how many key==T items to take (smallest indices)
    // items with key > T: all selected, arbitrary slot order
    for (int s = t; s < SEQ; s += 1024) {
        if (keys[s] > T) {
            int pos = atomicAdd(&s_cnt, 1);
            g_tk_idx[b*KSEL + pos] = s;
            g_tk_p[b*KSEL + pos]   = __uint_as_float(keys[s]);
        }
    }
    __syncthreads();
    int base = KSEL - rem;      // == s_cnt after the loop
    // items with key == T: take the 'rem' smallest indices, ranked by index
    for (int s = t; s < SEQ; s += 1024) {
        if (keys[s] == T) {
            int rank = 0;
            for (int j = 0; j < s; j++) rank += (keys[j] == T);
            if (rank < rem) {
                g_tk_idx[b*KSEL + base + rank] = s;
                g_tk_p[b*KSEL + base + rank]   = __uint_as_float(T);
            }
        }
    }
}

// ================= host orchestration =================
#define GEMM_SMEM (3*32768 + 128)
static inline void launch_gemm(const __half* ahi, const __half* alo,
                               const __half* bhi, const __half* blo,
                               float* C, __half* dhi, __half* dlo,
                               int M, int N, int K, int mode) {
    dim3 grid((N + 127)/128, (M + 127)/128);
    gemm_h3_k<<<grid, 256, GEMM_SMEM>>>(ahi, alo, bhi, blo, C, dhi, dlo, M, N, K, mode);
}

extern "C" void kernel_launch(void* const* d_in, const int* in_sizes, int n_in,
                              void* d_out, int out_size) {
    const int*   ids       = (const int*)d_in[0];
    const int*   iter      = (const int*)d_in[1];
    const float* emb       = (const float*)d_in[2];
    const float* iter_emb  = (const float*)d_in[3];
    const float* attn_norm = (const float*)d_in[4];
    const float* wqkv      = (const float*)d_in[5];
    const float* wo        = (const float*)d_in[6];
    const float* router    = (const float*)d_in[7];
    const float* mlp_norm  = (const float*)d_in[8];
    const float* gw        = (const float*)d_in[9];
    const float* uw        = (const float*)d_in[10];
    const float* dw        = (const float*)d_in[11];
    const float* fnorm     = (const float*)d_in[12];
    float* x = (float*)d_out;

    __half *ahi, *alo, *shi, *slo, *whi, *wlo;
    float *pqkv, *pprobs;
    cudaGetSymbolAddress((void**)&ahi,  g_ahi);
    cudaGetSymbolAddress((void**)&alo,  g_alo);
    cudaGetSymbolAddress((void**)&shi,  g_shi);
    cudaGetSymbolAddress((void**)&slo,  g_slo);
    cudaGetSymbolAddress((void**)&whi,  g_whi);
    cudaGetSymbolAddress((void**)&wlo,  g_wlo);
    cudaGetSymbolAddress((void**)&pqkv, g_qkv);
    cudaGetSymbolAddress((void**)&pprobs, g_probs);

    cudaFuncSetAttribute(fattn_tc_k, cudaFuncAttributeMaxDynamicSharedMemorySize, FA_SMEM);
    cudaFuncSetAttribute(gemm_h3_k, cudaFuncAttributeMaxDynamicSharedMemorySize, GEMM_SMEM);

    rope_table_k<<<(SEQ*32 + 255)/256, 256>>>();
    embed_k<<<(NTOK*DIM + 255)/256, 256>>>(ids, iter, emb, iter_emb, x);

    split_k<<<(LEN_QKV + 255)/256, 256>>>(wqkv, whi + OFF_QKV, wlo + OFF_QKV, LEN_QKV);
    split_k<<<(LEN_WO + 255)/256, 256>>>(wo, whi + OFF_WO, wlo + OFF_WO, LEN_WO);
    split_gu_int_k<<<(LEN_GU + 255)/256, 256>>>(gw, uw, whi + OFF_GU, wlo + OFF_GU);
    split_k<<<(LEN_DOWN + 255)/256, 256>>>(dw, whi + OFF_DOWN, wlo + OFF_DOWN, LEN_DOWN);

    for (int l = 0; l < NLAYER; l++) {
        const __half* qh = whi + OFF_QKV + (size_t)l*QKVN*DIM;
        const __half* ql = wlo + OFF_QKV + (size_t)l*QKVN*DIM;
        const __half* oh = whi + OFF_WO + (size_t)l*DIM*DIM;
        const __half* ol = wlo + OFF_WO + (size_t)l*DIM*DIM;
        const __half* gh = whi + OFF_GU + (size_t)l*2*FFD*DIM;
        const __half* gl = wlo + OFF_GU + (size_t)l*2*FFD*DIM;
        const __half* dh = whi + OFF_DOWN + (size_t)l*DIM*FFD;
        const __half* dl = wlo + OFF_DOWN + (size_t)l*DIM*FFD;

        rmsnorm_split_k<<<NTOK, DIM>>>(x, attn_norm + (size_t)l*DIM, ahi, alo, 0);
        launch_gemm(ahi, alo, qh, ql, pqkv, nullptr, nullptr, NTOK, QKVN, DIM, 0);
        rope_split_k<<<dim3(SEQ/64, NHEAD, BATCH), 256>>>(pqkv);
        fattn_tc_k<<<dim3(SEQ/128, NHEAD, BATCH), 256, FA_SMEM>>>(ahi, alo);
        launch_gemm(ahi, alo, oh, ol, x, nullptr, nullptr, NTOK, DIM, DIM, 1);

        router_prob_k<<<(NTOK+7)/8, 256>>>(x, router + (size_t)l*DIM, pprobs);
        topk_k<<<BATCH, 1024>>>(pprobs);

        rmsnorm_split_k<<<NSEL, DIM>>>(x, mlp_norm + (size_t)l*DIM, ahi, alo, 1);
        launch_gemm(ahi, alo, gh, gl, nullptr, shi, slo, NSEL, 2*FFD, DIM, 2);
        launch_gemm(shi, slo, dh, dl, x, nullptr, nullptr, NSEL, DIM, FFD, 3);
    }

    rmsnorm_plain_k<<<NTOK, DIM>>>(x, fnorm, x);
}

// round 12
// speedup vs baseline: 1.0225x; 1.0225x over previous
#include <cuda_runtime.h>
#include <cuda_fp16.h>
#include <math.h>
#include <stdint.h>

#define BATCH 8
#define SEQ   2048
#define DIM   320
#define NHEAD 5
#define HDIM  64
#define FFD   864
#define NLAYER 6
#define KSEL  1638
#define NTOK  (BATCH*SEQ)      // 16384
#define NSEL  (BATCH*KSEL)     // 13104
#define QKVN  (3*DIM)          // 960

// weight split buffer offsets (elements)
#define OFF_QKV  0
#define LEN_QKV  (NLAYER*QKVN*DIM)
#define OFF_WO   (OFF_QKV + LEN_QKV)
#define LEN_WO   (NLAYER*DIM*DIM)
#define OFF_GU   (OFF_WO + LEN_WO)
#define LEN_GU   (NLAYER*2*FFD*DIM)
#define OFF_DOWN (OFF_GU + LEN_GU)
#define LEN_DOWN (NLAYER*DIM*FFD)
#define W_TOTAL  (OFF_DOWN + LEN_DOWN)

// ---------------- scratch ----------------
__device__ __half g_ahi[(size_t)NTOK*DIM];
__device__ __half g_alo[(size_t)NTOK*DIM];
__device__ __half g_shi[(size_t)NSEL*FFD];
__device__ __half g_slo[(size_t)NSEL*FFD];
__device__ __half g_whi[W_TOTAL];
__device__ __half g_wlo[W_TOTAL];
__device__ float g_qkv[(size_t)NTOK*QKVN];
__device__ __half g_qkh[(size_t)NTOK*2*DIM];
__device__ __half g_qkl[(size_t)NTOK*2*DIM];
__device__ __half g_vth[(size_t)BATCH*NHEAD*HDIM*SEQ];
__device__ __half g_vtl[(size_t)BATCH*NHEAD*HDIM*SEQ];
__device__ float g_cos[SEQ*32];
__device__ float g_sin[SEQ*32];
__device__ int   g_tk_idx[BATCH*KSEL];
__device__ float g_tk_p[BATCH*KSEL];
__device__ float g_probs[NTOK];

__device__ __forceinline__ void split_h(float v, __half& h, __half& l) {
    h = __float2half_rn(v);
    l = __float2half_rn(v - __half2float(h));
}

// ================= PTX helpers =================
__device__ __forceinline__ uint32_t smem_u32(const void* p) {
    uint32_t a;
    asm("{ .reg .u64 t; cvta.to.shared.u64 t, %1; cvt.u32.u64 %0, t; }" : "=r"(a) : "l"(p));
    return a;
}
__device__ __forceinline__ void cp16(uint32_t dst, const void* src) {
    asm volatile("cp.async.cg.shared.global [%0], [%1], 16;" :: "r"(dst), "l"(src) : "memory");
}
__device__ __forceinline__ void ldsm4(uint32_t* r, uint32_t addr) {
    asm volatile("ldmatrix.sync.aligned.m8n8.x4.shared.b16 {%0,%1,%2,%3}, [%4];"
        : "=r"(r[0]), "=r"(r[1]), "=r"(r[2]), "=r"(r[3]) : "r"(addr));
}
__device__ __forceinline__ void mma16816(float* c, const uint32_t* a, const uint32_t* b) {
    asm volatile("mma.sync.aligned.m16n8k16.row.col.f32.f16.f16.f32 "
        "{%0,%1,%2,%3}, {%4,%5,%6,%7}, {%8,%9}, {%0,%1,%2,%3};"
        : "+f"(c[0]), "+f"(c[1]), "+f"(c[2]), "+f"(c[3])
        : "r"(a[0]), "r"(a[1]), "r"(a[2]), "r"(a[3]), "r"(b[0]), "r"(b[1]));
}
__device__ __forceinline__ uint32_t sw_addr(uint32_t base, int row, int chunk) {
    return base + (uint32_t)(row*128) + (uint32_t)(((chunk ^ (row & 7)))*16);
}

// ================= fp16x3 tensor-core GEMM (3-stage, single-sync mainloop) =================
// mode 0: C = A@B^T   mode 1: C += A@B^T
// mode 2: swiglu (B rows interleaved gate/up) -> Dhi/Dlo [M,FFD]
// mode 3: down + scatter into x
__global__ __launch_bounds__(256, 2)
void gemm_h3_k(const __half* __restrict__ Ahi, const __half* __restrict__ Alo,
               const __half* __restrict__ Bhi, const __half* __restrict__ Blo,
               float* __restrict__ C, __half* __restrict__ Dhi, __half* __restrict__ Dlo,
               int M, int N, int K, int mode)
{
    extern __shared__ char smem_raw[];
    uint32_t sb = (smem_u32(smem_raw) + 127u) & ~127u;

    const int t = threadIdx.x, lane = t & 31, wid = t >> 5;
    const int warp_m = wid & 1, warp_n = wid >> 1;
    const int m0 = blockIdx.y*128, n0 = blockIdx.x*128;
    const int T = K >> 5;
    const int l4 = lane >> 2, lm = lane & 3;

    const int lrow = t >> 1;
    const int lhalf = t & 1;
    const int aRow = min(m0 + lrow, M-1);
    const int bRow = min(n0 + lrow, N-1);
    const __half* aSrc = (lhalf ? Alo : Ahi) + (size_t)aRow*K;
    const __half* bSrc = (lhalf ? Blo : Bhi) + (size_t)bRow*K;
    uint32_t aDstBase = sb + (uint32_t)lrow*128u;
    uint32_t bDstBase = sb + 16384u + (uint32_t)lrow*128u;

    auto load_stage = [&](int kt, int s) {
        uint32_t so = (uint32_t)s*32768u;
        int k0 = kt*32;
        #pragma unroll
        for (int c4 = 0; c4 < 4; c4++) {
            int chunk = lhalf*4 + c4;
            uint32_t phys = (uint32_t)((chunk ^ (lrow & 7)) * 16);
            cp16(aDstBase + so + phys, aSrc + k0 + c4*8);
            cp16(bDstBase + so + phys, bSrc + k0 + c4*8);
        }
        asm volatile("cp.async.commit_group;" ::: "memory");
    };

    float accf[4][4][4];
    #pragma unroll
    for (int i = 0; i < 4; i++)
        #pragma unroll
        for (int j = 0; j < 4; j++)
            #pragma unroll
            for (int r = 0; r < 4; r++) accf[i][j][r] = 0.f;

    load_stage(0, 0);
    if (T > 1) load_stage(1, 1);
    if (T > 1) { asm volatile("cp.async.wait_group 1;" ::: "memory"); }
    else       { asm volatile("cp.async.wait_group 0;" ::: "memory"); }
    __syncthreads();

    const int rAl = (lane & 15);
    const int rBl = (lane & 7) + ((lane >> 4) << 3);
    const int chSelA = lane >> 4;
    const int chSelB = (lane >> 3) & 1;

    for (int kt = 0; kt < T; kt++) {
        int s = kt % 3;
        uint32_t Ab = sb + (uint32_t)s*32768u;
        uint32_t Bb = Ab + 16384u;
        // ---- compute on stage s (data guaranteed by previous wait+sync) ----
        #pragma unroll
        for (int ks = 0; ks < 2; ks++) {
            int chAh = ks*2 + chSelA, chAl = chAh + 4;
            int chBh = ks*2 + chSelB, chBl = chBh + 4;
            uint32_t BH[2][4], BL[2][4];
            #pragma unroll
            for (int nfp = 0; nfp < 2; nfp++) {
                int row = warp_n*32 + nfp*16 + rBl;
                ldsm4(BH[nfp], sw_addr(Bb, row, chBh));
                ldsm4(BL[nfp], sw_addr(Bb, row, chBl));
            }
            #pragma unroll
            for (int mf = 0; mf < 4; mf++) {
                int row = warp_m*64 + mf*16 + rAl;
                uint32_t AH4[4], AL4[4];
                ldsm4(AH4, sw_addr(Ab, row, chAh));
                ldsm4(AL4, sw_addr(Ab, row, chAl));
                #pragma unroll
                for (int nfp = 0; nfp < 2; nfp++) {
                    #pragma unroll
                    for (int sub = 0; sub < 2; sub++) {
                        int nf = nfp*2 + sub;
                        mma16816(accf[mf][nf], AH4, BH[nfp] + sub*2);
                        mma16816(accf[mf][nf], AH4, BL[nfp] + sub*2);
                        mma16816(accf[mf][nf], AL4, BH[nfp] + sub*2);
                    }
                }
            }
        }
        // ---- prefetch stage kt+2 (overwrites stage read at kt-1; safe past prev sync) ----
        if (kt + 2 < T) load_stage(kt + 2, (kt + 2) % 3);
        if (kt + 1 < T) {
            if (kt + 2 < T) { asm volatile("cp.async.wait_group 1;" ::: "memory"); }
            else            { asm volatile("cp.async.wait_group 0;" ::: "memory"); }
            __syncthreads();
        }
    }

    // ---- epilogue ----
    #pragma unroll
    for (int mf = 0; mf < 4; mf++) {
        int r0 = m0 + warp_m*64 + mf*16 + l4;
        int r1 = r0 + 8;
        #pragma unroll
        for (int nf = 0; nf < 4; nf++) {
            int c = n0 + warp_n*32 + nf*8 + lm*2;
            if (c >= N) continue;
            float v0 = accf[mf][nf][0], v1 = accf[mf][nf][1];
            float v2 = accf[mf][nf][2], v3 = accf[mf][nf][3];
            if (mode <= 1) {
                if (r0 < M) {
                    float* p = C + (size_t)r0*N + c;
                    if (mode) { v0 += p[0]; v1 += p[1]; }
                    p[0] = v0; p[1] = v1;
                }
                if (r1 < M) {
                    float* p = C + (size_t)r1*N + c;
                    if (mode) { v2 += p[0]; v3 += p[1]; }
                    p[0] = v2; p[1] = v3;
                }
            } else if (mode == 2) {
                int j = c >> 1;
                if (r0 < M) {
                    float o = (v0 / (1.f + expf(-v0))) * v1;
                    __half h, l; split_h(o, h, l);
                    Dhi[(size_t)r0*FFD + j] = h; Dlo[(size_t)r0*FFD + j] = l;
                }
                if (r1 < M) {
                    float o = (v2 / (1.f + expf(-v2))) * v3;
                    __half h, l; split_h(o, h, l);
                    Dhi[(size_t)r1*FFD + j] = h; Dlo[(size_t)r1*FFD + j] = l;
                }
            } else {
                if (r0 < M) {
                    int b = r0 / KSEL;
                    float pp = g_tk_p[r0];
                    float* p = C + ((size_t)b*SEQ + g_tk_idx[r0])*DIM + c;
                    p[0] += v0*pp; p[1] += v1*pp;
                }
                if (r1 < M) {
                    int b = r1 / KSEL;
                    float pp = g_tk_p[r1];
                    float* p = C + ((size_t)b*SEQ + g_tk_idx[r1])*DIM + c;
                    p[0] += v2*pp; p[1] += v3*pp;
                }
            }
        }
    }
}

// ================= small kernels =================
__global__ void rope_table_k() {
    int i = blockIdx.x*blockDim.x + threadIdx.x;
    if (i >= SEQ*32) return;
    int s = i >> 5, d = i & 31;
    double freq = exp(-((double)(2*d)/(double)HDIM) * log(10000.0));
    double a = (double)s * freq;
    g_cos[i] = (float)cos(a);
    g_sin[i] = (float)sin(a);
}

__global__ void embed_k(const int* __restrict__ ids, const int* __restrict__ iter,
                        const float* __restrict__ emb, const float* __restrict__ iter_emb,
                        float* __restrict__ x) {
    int i = blockIdx.x*blockDim.x + threadIdx.x;
    if (i >= NTOK*DIM) return;
    int tok = i / DIM, d = i - tok*DIM;
    int it = iter[0];
    float v = emb[(size_t)ids[tok]*DIM + d];
    if (it < 8) v += iter_emb[(size_t)it*DIM + d];
    x[i] = v;
}

// split A: wqkv then wo -> g_whi/g_wlo at [0, LEN_QKV+LEN_WO)
__global__ void split_a_k(const float* __restrict__ wqkv, const float* __restrict__ wo,
                          __half* __restrict__ hi, __half* __restrict__ lo) {
    int i = blockIdx.x*blockDim.x + threadIdx.x;
    if (i >= LEN_QKV + LEN_WO) return;
    float a = (i < LEN_QKV) ? wqkv[i] : wo[i - LEN_QKV];
    __half h, l; split_h(a, h, l);
    hi[i] = h; lo[i] = l;
}

// split B: gate/up interleaved then down -> g_whi/g_wlo at [OFF_GU, W_TOTAL)
__global__ void split_b_k(const float* __restrict__ gw, const float* __restrict__ uw,
                          const float* __restrict__ dw,
                          __half* __restrict__ hi, __half* __restrict__ lo) {
    int i = blockIdx.x*blockDim.x + threadIdx.x;
    if (i >= LEN_GU + LEN_DOWN) return;
    float a;
    if (i < LEN_GU) {
        int l = i / (2*FFD*DIM), rr = i % (2*FFD*DIM);
        int row = rr / DIM, d = rr - row*DIM;
        int j = row >> 1;
        const float* src = (row & 1) ? uw : gw;
        a = src[(size_t)l*FFD*DIM + (size_t)j*DIM + d];
    } else {
        a = dw[i - LEN_GU];
    }
    __half h, l; split_h(a, h, l);
    hi[OFF_GU + i] = h; lo[OFF_GU + i] = l;
}

__global__ void rmsnorm_split_k(const float* __restrict__ in, const float* __restrict__ w,
                                __half* __restrict__ ohi, __half* __restrict__ olo, int gather) {
    int r = blockIdx.x, t = threadIdx.x;   // 320 threads
    size_t src;
    if (gather) {
        int b = r / KSEL;
        src = ((size_t)b*SEQ + g_tk_idx[r]) * DIM;
    } else {
        src = (size_t)r * DIM;
    }
    float v = in[src + t];
    float sq = v*v;
    #pragma unroll
    for (int o = 16; o > 0; o >>= 1) sq += __shfl_down_sync(0xffffffffu, sq, o);
    __shared__ float wsum[10];
    __shared__ float s_inv;
    if ((t & 31) == 0) wsum[t >> 5] = sq;
    __syncthreads();
    if (t == 0) {
        float s = 0.f;
        #pragma unroll
        for (int i = 0; i < 10; i++) s += wsum[i];
        s_inv = rsqrtf(s / (float)DIM + 1e-6f);
    }
    __syncthreads();
    float y = w[t] * v * s_inv;
    __half h, l; split_h(y, h, l);
    ohi[(size_t)r*DIM + t] = h;
    olo[(size_t)r*DIM + t] = l;
}

__global__ void rmsnorm_plain_k(const float* __restrict__ in, const float* __restrict__ w,
                                float* __restrict__ out) {
    int r = blockIdx.x, t = threadIdx.x;
    float v = in[(size_t)r*DIM + t];
    float sq = v*v;
    #pragma unroll
    for (int o = 16; o > 0; o >>= 1) sq += __shfl_down_sync(0xffffffffu, sq, o);
    __shared__ float wsum[10];
    __shared__ float s_inv;
    if ((t & 31) == 0) wsum[t >> 5] = sq;
    __syncthreads();
    if (t == 0) {
        float s = 0.f;
        #pragma unroll
        for (int i = 0; i < 10; i++) s += wsum[i];
        s_inv = rsqrtf(s / (float)DIM + 1e-6f);
    }
    __syncthreads();
    out[(size_t)r*DIM + t] = w[t] * v * s_inv;
}

// ---- rope + split q/k + transpose/split v ----
__global__ __launch_bounds__(256)
void rope_split_k(const float* __restrict__ qkv) {
    __shared__ float vt[64][65];
    int st = blockIdx.x*64, h = blockIdx.y, b = blockIdx.z;
    int t = threadIdx.x;
    const float* base = qkv + ((size_t)b*SEQ + st)*QKVN;

    #pragma unroll
    for (int k = 0; k < 16; k++) {
        int i = t + k*256;
        int s = i >> 6, d = i & 63;
        vt[d][s] = base[(size_t)s*QKVN + 2*DIM + h*HDIM + d];
    }
    __syncthreads();
    {
        size_t vbase = ((size_t)(b*NHEAD + h))*HDIM*SEQ;
        #pragma unroll
        for (int k = 0; k < 16; k++) {
            int i = t + k*256;
            int d = i >> 6, s = i & 63;
            float v = vt[d][s];
            __half hh, ll; split_h(v, hh, ll);
            size_t o = vbase + (size_t)d*SEQ + st + s;
            g_vth[o] = hh; g_vtl[o] = ll;
        }
    }
    #pragma unroll
    for (int part = 0; part < 2; part++) {
        #pragma unroll
        for (int k = 0; k < 8; k++) {
            int i = t + k*256;
            int tok = i >> 5, d = i & 31;
            int s = st + tok;
            float c = g_cos[s*32 + d], sn = g_sin[s*32 + d];
            const float* p = base + (size_t)tok*QKVN + part*DIM + h*HDIM;
            float a = p[d], bb = p[d+32];
            float o0 = a*c - bb*sn;
            float o1 = bb*c + a*sn;
            if (part == 0) { o0 *= 0.125f; o1 *= 0.125f; }
            size_t ob = ((size_t)b*SEQ + s)*(2*DIM) + part*DIM + h*HDIM;
            __half h0, l0, h1, l1;
            split_h(o0, h0, l0); split_h(o1, h1, l1);
            g_qkh[ob + d] = h0;      g_qkl[ob + d] = l0;
            g_qkh[ob + d + 32] = h1; g_qkl[ob + d + 32] = l1;
        }
    }
}

// ---------------- tensor-core flash attention: 128-q tile, 256 threads ----------------
#define FA_SMEM (32768 + 2*32768 + 128)
__global__ __launch_bounds__(256, 2)
void fattn_tc_k(__half* __restrict__ ohi, __half* __restrict__ olo) {
    extern __shared__ char smem_raw[];
    uint32_t sb = (smem_u32(smem_raw) + 127u) & ~127u;
    const uint32_t QH = sb, QL = sb + 16384;
    const int t = threadIdx.x, lane = t & 31, warp = t >> 5;
    const int l4 = lane >> 2, lm = lane & 3;
    const int wr = warp*16;
    const int qt = gridDim.x - 1 - blockIdx.x;
    const int h = blockIdx.y, b = blockIdx.z;
    const int q0 = qt*128;
    const int ktmax = 2*qt + 1;

    {
        int row = t & 127, cg = t >> 7;
        size_t qoff = ((size_t)b*SEQ + q0 + row)*(2*DIM) + h*HDIM;
        #pragma unroll
        for (int c4 = 0; c4 < 4; c4++) {
            int c = cg*4 + c4;
            uint32_t phys = (uint32_t)(row*128) + (uint32_t)(((c ^ (row&7)))*16);
            cp16(QH + phys, g_qkh + qoff + c*8);
            cp16(QL + phys, g_qkl + qoff + c*8);
        }
    }
    const int lr = t & 63, cg2 = t >> 6;
    size_t vtb = ((size_t)(b*NHEAD + h))*HDIM*SEQ + (size_t)lr*SEQ;

    auto load_stage = [&](int kt, int s) {
        uint32_t sbase = sb + 32768u + (uint32_t)s*32768u;
        int k0 = kt*64;
        size_t koff = ((size_t)b*SEQ + k0 + lr)*(2*DIM) + DIM + h*HDIM;
        #pragma unroll
        for (int c4 = 0; c4 < 2; c4++) {
            int c = cg2*2 + c4;
            uint32_t phys = (uint32_t)(lr*128) + (uint32_t)(((c ^ (lr&7)))*16);
            cp16(sbase          + phys, g_qkh + koff + c*8);
            cp16(sbase +  8192u + phys, g_qkl + koff + c*8);
            cp16(sbase + 16384u + phys, g_vth + vtb + k0 + c*8);
            cp16(sbase + 24576u + phys, g_vtl + vtb + k0 + c*8);
        }
        asm volatile("cp.async.commit_group;" ::: "memory");
    };

    load_stage(0, 0);

    float oacc[8][4];
    #pragma unroll
    for (int i = 0; i < 8; i++)
        #pragma unroll
        for (int j = 0; j < 4; j++) oacc[i][j] = 0.f;
    float m0 = -1e30f, m1 = -1e30f, l0 = 0.f, l1 = 0.f;

    const int rAl = (lane & 15);
    const int rBl = (lane & 7) + ((lane >> 4) << 3);
    const int chSelA = lane >> 4;
    const int chSelB = (lane >> 3) & 1;

    for (int kt = 0; kt <= ktmax; kt++) {
        int s = kt & 1;
        if (kt < ktmax) {
            load_stage(kt + 1, s ^ 1);
            asm volatile("cp.async.wait_group 1;" ::: "memory");
        } else {
            asm volatile("cp.async.wait_group 0;" ::: "memory");
        }
        __syncthreads();
        uint32_t KHs = sb + 32768u + (uint32_t)s*32768u;
        uint32_t KLs = KHs + 8192u, VHs = KHs + 16384u, VLs = KHs + 24576u;
        int k0 = kt*64;

        // ---- S = Q K^T (fp16x3) ----
        float sacc[8][4];
        #pragma unroll
        for (int i = 0; i < 8; i++)
            #pragma unroll
            for (int j = 0; j < 4; j++) sacc[i][j] = 0.f;

        #pragma unroll
        for (int ks = 0; ks < 4; ks++) {
            int chA = ks*2 + chSelA;
            int chB = ks*2 + chSelB;
            uint32_t aqh[4], aql[4];
            int rowq = wr + rAl;
            ldsm4(aqh, sw_addr(QH, rowq, chA));
            ldsm4(aql, sw_addr(QL, rowq, chA));
            #pragma unroll
            for (int nfp = 0; nfp < 4; nfp++) {
                int rowk = nfp*16 + rBl;
                uint32_t bh4[4], bl4[4];
                ldsm4(bh4, sw_addr(KHs, rowk, chB));
                ldsm4(bl4, sw_addr(KLs, rowk, chB));
                #pragma unroll
                for (int sub = 0; sub < 2; sub++) {
                    int nf = nfp*2 + sub;
                    mma16816(sacc[nf], aqh, bh4 + sub*2);
                    mma16816(sacc[nf], aqh, bl4 + sub*2);
                    mma16816(sacc[nf], aql, bh4 + sub*2);
                }
            }
        }

        if (k0 + 63 > q0 + wr) {
            int r0g = q0 + wr + l4, r1g = r0g + 8;
            #pragma unroll
            for (int nf = 0; nf < 8; nf++) {
                int c = k0 + nf*8 + lm*2;
                if (c     > r0g) sacc[nf][0] = -1e30f;
                if (c + 1 > r0g) sacc[nf][1] = -1e30f;
                if (c     > r1g) sacc[nf][2] = -1e30f;
                if (c + 1 > r1g) sacc[nf][3] = -1e30f;
            }
        }

        // ---- online softmax ----
        float mx0 = -1e30f, mx1 = -1e30f;
        #pragma unroll
        for (int nf = 0; nf < 8; nf++) {
            mx0 = fmaxf(mx0, fmaxf(sacc[nf][0], sacc[nf][1]));
            mx1 = fmaxf(mx1, fmaxf(sacc[nf][2], sacc[nf][3]));
        }
        mx0 = fmaxf(mx0, __shfl_xor_sync(0xffffffffu, mx0, 1));
        mx0 = fmaxf(mx0, __shfl_xor_sync(0xffffffffu, mx0, 2));
        mx1 = fmaxf(mx1, __shfl_xor_sync(0xffffffffu, mx1, 1));
        mx1 = fmaxf(mx1, __shfl_xor_sync(0xffffffffu, mx1, 2));
        float mn0 = fmaxf(m0, mx0), mn1 = fmaxf(m1, mx1);
        float cr0 = __expf(m0 - mn0), cr1 = __expf(m1 - mn1);
        m0 = mn0; m1 = mn1;
        float rs0 = 0.f, rs1 = 0.f;
        #pragma unroll
        for (int nf = 0; nf < 8; nf++) {
            sacc[nf][0] = __expf(sacc[nf][0] - mn0); rs0 += sacc[nf][0];
            sacc[nf][1] = __expf(sacc[nf][1] - mn0); rs0 += sacc[nf][1];
            sacc[nf][2] = __expf(sacc[nf][2] - mn1); rs1 += sacc[nf][2];
            sacc[nf][3] = __expf(sacc[nf][3] - mn1); rs1 += sacc[nf][3];
        }
        rs0 += __shfl_xor_sync(0xffffffffu, rs0, 1);
        rs0 += __shfl_xor_sync(0xffffffffu, rs0, 2);
        rs1 += __shfl_xor_sync(0xffffffffu, rs1, 1);
        rs1 += __shfl_xor_sync(0xffffffffu, rs1, 2);
        l0 = l0*cr0 + rs0;
        l1 = l1*cr1 + rs1;
        #pragma unroll
        for (int df = 0; df < 8; df++) {
            oacc[df][0] *= cr0; oacc[df][1] *= cr0;
            oacc[df][2] *= cr1; oacc[df][3] *= cr1;
        }

        // ---- O += P V (fp16x3) ----
        #pragma unroll
        for (int ks = 0; ks < 4; ks++) {
            uint32_t aPh[4], aPl[4];
            #pragma unroll
            for (int h2 = 0; h2 < 2; h2++) {
                int nf = 2*ks + h2;
                __half h0, e0, h1, e1, h2h, e2, h3, e3;
                split_h(sacc[nf][0], h0, e0); split_h(sacc[nf][1], h1, e1);
                split_h(sacc[nf][2], h2h, e2); split_h(sacc[nf][3], h3, e3);
                __half2 ph01 = __halves2half2(h0, h1), pl01 = __halves2half2(e0, e1);
                __half2 ph23 = __halves2half2(h2h, h3), pl23 = __halves2half2(e2, e3);
                aPh[h2*2 + 0] = *(uint32_t*)&ph01;
                aPh[h2*2 + 1] = *(uint32_t*)&ph23;
                aPl[h2*2 + 0] = *(uint32_t*)&pl01;
                aPl[h2*2 + 1] = *(uint32_t*)&pl23;
            }
            int chB = ks*2 + chSelB;
            #pragma unroll
            for (int dfp = 0; dfp < 4; dfp++) {
                int rowv = dfp*16 + rBl;
                uint32_t bh4[4], bl4[4];
                ldsm4(bh4, sw_addr(VHs, rowv, chB));
                ldsm4(bl4, sw_addr(VLs, rowv, chB));
                #pragma unroll
                for (int sub = 0; sub < 2; sub++) {
                    int df = dfp*2 + sub;
                    mma16816(oacc[df], aPh, bh4 + sub*2);
                    mma16816(oacc[df], aPh, bl4 + sub*2);
                    mma16816(oacc[df], aPl, bh4 + sub*2);
                }
            }
        }
        __syncthreads();
    }

    float inv0 = 1.f / l0, inv1 = 1.f / l1;
    int r0 = q0 + wr + l4, r1 = r0 + 8;
    #pragma unroll
    for (int df = 0; df < 8; df++) {
        int d = df*8 + lm*2;
        float v0 = oacc[df][0]*inv0, v1 = oacc[df][1]*inv0;
        float v2 = oacc[df][2]*inv1, v3 = oacc[df][3]*inv1;
        __half h0, e0, h1, e1, h2, e2, h3, e3;
        split_h(v0, h0, e0); split_h(v1, h1, e1);
        split_h(v2, h2, e2); split_h(v3, h3, e3);
        size_t o0 = ((size_t)b*SEQ + r0)*DIM + h*HDIM + d;
        size_t o1 = ((size_t)b*SEQ + r1)*DIM + h*HDIM + d;
        *(__half2*)(ohi + o0) = __halves2half2(h0, h1);
        *(__half2*)(olo + o0) = __halves2half2(e0, e1);
        *(__half2*)(ohi + o1) = __halves2half2(h2, h3);
        *(__half2*)(olo + o1) = __halves2half2(e2, e3);
    }
}

// ---------------- router + topk ----------------
__global__ __launch_bounds__(256)
void router_prob_k(const float* __restrict__ x, const float* __restrict__ rw,
                   float* __restrict__ probs) {
    int tok = blockIdx.x*8 + (threadIdx.x >> 5);
    int lane = threadIdx.x & 31;
    if (tok >= NTOK) return;
    const float* row = x + (size_t)tok*DIM;
    float acc = 0.f;
    #pragma unroll
    for (int i = 0; i < 10; i++) acc += row[lane + 32*i]*rw[lane + 32*i];
    #pragma unroll
    for (int o = 16; o > 0; o >>= 1) acc += __shfl_xor_sync(0xffffffffu, acc, o);
    if (lane == 0) probs[tok] = 1.f/(1.f + expf(-acc));
}

// radix-select top-k (prob desc, ties -> smaller idx; matches jax.lax.top_k)
__global__ __launch_bounds__(1024)
void topk_k(const float* __restrict__ probs) {
    int b = blockIdx.x, t = threadIdx.x;
    __shared__ uint32_t keys[SEQ];
    __shared__ int hist[256];
    __shared__ uint32_t s_prefix;
    __shared__ int s_remaining;
    __shared__ int s_cnt;

    for (int s = t; s < SEQ; s += 1024) keys[s] = __float_as_uint(probs[b*SEQ + s]);
    if (t == 0) { s_prefix = 0; s_remaining = KSEL; s_cnt = 0; }
    __syncthreads();

    for (int pass = 0; pass < 4; pass++) {
        int shift = 24 - pass*8;
        uint32_t mask = (pass == 0) ? 0u : (0xFFFFFFFFu << (shift + 8));
        if (t < 256) hist[t] = 0;
        __syncthreads();
        uint32_t pfx = s_prefix;
        for (int s = t; s < SEQ; s += 1024) {
            uint32_t kk = keys[s];
            if ((kk & mask) == (pfx & mask))
                atomicAdd(&hist[(kk >> shift) & 255], 1);
        }
        __syncthreads();
        if (t == 0) {
            int acc = 0, bin = 255;
            for (; bin > 0; bin--) {
                if (acc + hist[bin] >= s_remaining) break;
                acc += hist[bin];
            }
            s_prefix |= (uint32_t)bin << shift;
            s_remaining -= acc;
        }
        __syncthreads();
    }

    uint32_t T = s_prefix;
    int rem = s_remaining;
    for (int s = t; s < SEQ; s += 1024) {
        if (keys[s] > T) {
            int pos = atomicAdd(&s_cnt, 1);
            g_tk_idx[b*KSEL + pos] = s;
            g_tk_p[b*KSEL + pos]   = __uint_as_float(keys[s]);
        }
    }
    __syncthreads();
    int base = KSEL - rem;
    for (int s = t; s < SEQ; s += 1024) {
        if (keys[s] == T) {
            int rank = 0;
            for (int j = 0; j < s; j++) rank += (keys[j] == T);
            if (rank < rem) {
                g_tk_idx[b*KSEL + base + rank] = s;
                g_tk_p[b*KSEL + base + rank]   = __uint_as_float(T);
            }
        }
    }
}

// ================= host orchestration =================
#define GEMM_SMEM (3*32768 + 128)
static inline void launch_gemm(const __half* ahi, const __half* alo,
                               const __half* bhi, const __half* blo,
                               float* C, __half* dhi, __half* dlo,
                               int M, int N, int K, int mode) {
    dim3 grid((N + 127)/128, (M + 127)/128);
    gemm_h3_k<<<grid, 256, GEMM_SMEM>>>(ahi, alo, bhi, blo, C, dhi, dlo, M, N, K, mode);
}

extern "C" void kernel_launch(void* const* d_in, const int* in_sizes, int n_in,
                              void* d_out, int out_size) {
    const int*   ids       = (const int*)d_in[0];
    const int*   iter      = (const int*)d_in[1];
    const float* emb       = (const float*)d_in[2];
    const float* iter_emb  = (const float*)d_in[3];
    const float* attn_norm = (const float*)d_in[4];
    const float* wqkv      = (const float*)d_in[5];
    const float* wo        = (const float*)d_in[6];
    const float* router    = (const float*)d_in[7];
    const float* mlp_norm  = (const float*)d_in[8];
    const float* gw        = (const float*)d_in[9];
    const float* uw        = (const float*)d_in[10];
    const float* dw        = (const float*)d_in[11];
    const float* fnorm     = (const float*)d_in[12];
    float* x = (float*)d_out;

    __half *ahi, *alo, *shi, *slo, *whi, *wlo;
    float *pqkv, *pprobs;
    cudaGetSymbolAddress((void**)&ahi,  g_ahi);
    cudaGetSymbolAddress((void**)&alo,  g_alo);
    cudaGetSymbolAddress((void**)&shi,  g_shi);
    cudaGetSymbolAddress((void**)&slo,  g_slo);
    cudaGetSymbolAddress((void**)&whi,  g_whi);
    cudaGetSymbolAddress((void**)&wlo,  g_wlo);
    cudaGetSymbolAddress((void**)&pqkv, g_qkv);
    cudaGetSymbolAddress((void**)&pprobs, g_probs);

    cudaFuncSetAttribute(fattn_tc_k, cudaFuncAttributeMaxDynamicSharedMemorySize, FA_SMEM);
    cudaFuncSetAttribute(gemm_h3_k, cudaFuncAttributeMaxDynamicSharedMemorySize, GEMM_SMEM);

    // launches 1-4 (so launch #6 = first gemm_h3_k lands in ncu's -s 5 -c 1 window)
    rope_table_k<<<(SEQ*32 + 255)/256, 256>>>();
    embed_k<<<(NTOK*DIM + 255)/256, 256>>>(ids, iter, emb, iter_emb, x);
    split_a_k<<<(LEN_QKV + LEN_WO + 255)/256, 256>>>(wqkv, wo, whi, wlo);
    split_b_k<<<(LEN_GU + LEN_DOWN + 255)/256, 256>>>(gw, uw, dw, whi, wlo);

    for (int l = 0; l < NLAYER; l++) {
        const __half* qh = whi + OFF_QKV + (size_t)l*QKVN*DIM;
        const __half* ql = wlo + OFF_QKV + (size_t)l*QKVN*DIM;
        const __half* oh = whi + OFF_WO + (size_t)l*DIM*DIM;
        const __half* ol = wlo + OFF_WO + (size_t)l*DIM*DIM;
        const __half* gh = whi + OFF_GU + (size_t)l*2*FFD*DIM;
        const __half* gl = wlo + OFF_GU + (size_t)l*2*FFD*DIM;
        const __half* dh = whi + OFF_DOWN + (size_t)l*DIM*FFD;
        const __half* dl = wlo + OFF_DOWN + (size_t)l*DIM*FFD;

        rmsnorm_split_k<<<NTOK, DIM>>>(x, attn_norm + (size_t)l*DIM, ahi, alo, 0);
        launch_gemm(ahi, alo, qh, ql, pqkv, nullptr, nullptr, NTOK, QKVN, DIM, 0);
        rope_split_k<<<dim3(SEQ/64, NHEAD, BATCH), 256>>>(pqkv);
        fattn_tc_k<<<dim3(SEQ/128, NHEAD, BATCH), 256, FA_SMEM>>>(ahi, alo);
        launch_gemm(ahi, alo, oh, ol, x, nullptr, nullptr, NTOK, DIM, DIM, 1);

        router_prob_k<<<(NTOK+7)/8, 256>>>(x, router + (size_t)l*DIM, pprobs);
        topk_k<<<BATCH, 1024>>>(pprobs);

        rmsnorm_split_k<<<NSEL, DIM>>>(x, mlp_norm + (size_t)l*DIM, ahi, alo, 1);
        launch_gemm(ahi, alo, gh, gl, nullptr, shi, slo, NSEL, 2*FFD, DIM, 2);
        launch_gemm(shi, slo, dh, dl, x, nullptr, nullptr, NSEL, DIM, FFD, 3);
    }

    rmsnorm_plain_k<<<NTOK, DIM>>>(x, fnorm, x);
}